// round 5
// baseline (speedup 1.0000x reference)
#include <cuda_runtime.h>
#include <math.h>

// Fixed problem shapes:
// feat0 [2,256,200,200] f32, feat1 [2,256,100,100], feat2 [2,256,50,50],
// feat3 [2,256,25,25], boxes [2,256,4] f32 -> out [512,256,7,7] f32.
#define KROIS   512
#define NC      256
#define OUTHW   7
#define NBINS   49
#define WARPS   8               // warps per block, 1 channel each
#define GRPS    (NC / WARPS)    // 32 channel-groups per roi
#define TSTRIDE 29              // temp row stride (28 + 1 pad)

__device__ __forceinline__ void prep_coord(float c, int size,
                                           int& lo, int& hi, float& l, float& h)
{
    c = fmaxf(c, 0.0f);
    lo = (int)c;
    if (lo >= size - 1) { lo = size - 1; hi = size - 1; }
    else                { hi = lo + 1; }
    l = c - (float)lo;
    h = 1.0f - l;
}

__global__ void __launch_bounds__(256)
roi_align_mlp_kernel(const float* __restrict__ f0,
                     const float* __restrict__ f1,
                     const float* __restrict__ f2,
                     const float* __restrict__ f3,
                     const float* __restrict__ boxes,
                     float* __restrict__ out)
{
    // per-warp tables -> no block-wide barriers anywhere
    __shared__ int4   s_yoff[WARPS][OUTHW];  // row offsets premultiplied by W
    __shared__ float4 s_yw[WARPS][OUTHW];    // (hy0, ly0, hy1, ly1)
    __shared__ float  s_temp[WARPS][OUTHW * TSTRIDE];

    const int k    = blockIdx.x >> 5;          // roi
    const int grp  = blockIdx.x & (GRPS - 1);
    const int tid  = threadIdx.x;
    const int warp = tid >> 5;
    const int lane = tid & 31;

    // ---- per-roi scalars: every thread redundantly (no serialization) ----
    const float4 bx = __ldg((const float4*)boxes + k);
    const float x1 = bx.x, y1 = bx.y, x2 = bx.z, y2 = bx.w;

    float area = (x2 - x1) * (y2 - y1);
    float s    = sqrtf(area);
    float lvl  = floorf(4.0f + log2f(s / 224.0f) + 1e-6f);
    lvl = fminf(fmaxf(lvl, 2.0f), 5.0f);
    const int level = (int)lvl - 2;

    const float scales[4] = {0.25f, 0.125f, 0.0625f, 0.03125f};
    const int   dims[4]   = {200, 100, 50, 25};
    const float sc = scales[level];
    const int   W  = dims[level];

    const float x1s = x1 * sc, y1s = y1 * sc;
    const float x2s = x2 * sc, y2s = y2 * sc;
    const float bin_w = fmaxf(x2s - x1s, 1.0f) / (float)OUTHW;
    const float bin_h = fmaxf(y2s - y1s, 1.0f) / (float)OUTHW;

    // ---- y tables: lanes 0-6 of each warp ----
    if (lane < OUTHW) {
        int p = lane;
        float half = bin_h * 0.5f;
        int lo0, hi0, lo1, hi1; float l0, h0, l1, h1;
        prep_coord(y1s + (float)p * bin_h + 0.5f * half, W, lo0, hi0, l0, h0);
        prep_coord(y1s + (float)p * bin_h + 1.5f * half, W, lo1, hi1, l1, h1);
        s_yoff[warp][p] = make_int4(lo0 * W, hi0 * W, lo1 * W, hi1 * W);
        s_yw[warp][p]   = make_float4(h0, l0, h1, l1);
    }

    // ---- per-lane x corner: j = 4*pw + 2*ix + corner (lanes 28-31 mirror 27) ----
    const int j      = (lane < 28) ? lane : 27;
    const int si     = j >> 1;
    const int corner = j & 1;
    const int pwj    = si >> 1;
    const int ixj    = si & 1;

    float half_bw = bin_w * 0.5f;
    int xlo, xhi; float xl, xh;
    prep_coord(x1s + (float)pwj * bin_w + ((float)ixj + 0.5f) * half_bw, W,
               xlo, xhi, xl, xh);
    const int   xc = corner ? xhi : xlo;
    const float xw = 0.25f * (corner ? xl : xh);

    const int c = grp * WARPS + warp;
    const int b = k >> 8;

    const float* feat;
    switch (level) {
        case 0:  feat = f0; break;
        case 1:  feat = f1; break;
        case 2:  feat = f2; break;
        default: feat = f3; break;
    }
    const float* __restrict__ pbase =
        feat + (size_t)((b * NC + c) * W) * (size_t)W + xc;

    __syncwarp();

    // ---- phase A: batch ALL 28 loads into registers first (max MLP) ----
    int4 ro[OUTHW];
    #pragma unroll
    for (int ph = 0; ph < OUTHW; ph++) ro[ph] = s_yoff[warp][ph];

    float v[OUTHW][4];
    #pragma unroll
    for (int ph = 0; ph < OUTHW; ph++) {
        v[ph][0] = __ldg(pbase + ro[ph].x);
        v[ph][1] = __ldg(pbase + ro[ph].y);
        v[ph][2] = __ldg(pbase + ro[ph].z);
        v[ph][3] = __ldg(pbase + ro[ph].w);
    }

    float* __restrict__ tw = s_temp[warp];
    #pragma unroll
    for (int ph = 0; ph < OUTHW; ph++) {
        float4 yw = s_yw[warp][ph];
        float a = yw.x * v[ph][0] + yw.y * v[ph][1]
                + yw.z * v[ph][2] + yw.w * v[ph][3];
        if (lane < 28) tw[ph * TSTRIDE + j] = a * xw;
    }
    __syncwarp();

    // ---- phase B: out[ph][pw] = sum of 4 temp entries (R3 scheme) ----
    const size_t obase = (size_t)(k * NC + c) * NBINS;
    #pragma unroll
    for (int o = lane; o < NBINS; o += 32) {
        int ph = o / OUTHW;
        int pw = o - ph * OUTHW;
        const float* t = tw + ph * TSTRIDE + pw * 4;
        out[obase + o] = (t[0] + t[1]) + (t[2] + t[3]);
    }
}

extern "C" void kernel_launch(void* const* d_in, const int* in_sizes, int n_in,
                              void* d_out, int out_size)
{
    const float* f0    = (const float*)d_in[0];
    const float* f1    = (const float*)d_in[1];
    const float* f2    = (const float*)d_in[2];
    const float* f3    = (const float*)d_in[3];
    const float* boxes = (const float*)d_in[4];
    float* out = (float*)d_out;

    const int blocks = KROIS * GRPS;   // 16384
    roi_align_mlp_kernel<<<blocks, 256>>>(f0, f1, f2, f3, boxes, out);
}

// round 6
// speedup vs baseline: 1.2287x; 1.2287x over previous
#include <cuda_runtime.h>
#include <math.h>

// Fixed problem shapes:
// feat0 [2,256,200,200] f32, feat1 [2,256,100,100], feat2 [2,256,50,50],
// feat3 [2,256,25,25], boxes [2,256,4] f32 -> out [512,256,7,7] f32.
#define KROIS   512
#define NC      256
#define OUTHW   7
#define NBINS   49
#define WARPS   8               // warps per block
#define CPW     2               // channels per warp
#define CPB     (WARPS * CPW)   // 16 channels per block
#define GRPS    (NC / CPB)      // 16 channel-groups per roi
#define TSTRIDE 29              // temp row stride (28 + 1 pad)

__device__ __forceinline__ void prep_coord(float c, int size,
                                           int& lo, int& hi, float& l, float& h)
{
    c = fmaxf(c, 0.0f);
    lo = (int)c;
    if (lo >= size - 1) { lo = size - 1; hi = size - 1; }
    else                { hi = lo + 1; }
    l = c - (float)lo;
    h = 1.0f - l;
}

__global__ void __launch_bounds__(256)
roi_align_2ch_kernel(const float* __restrict__ f0,
                     const float* __restrict__ f1,
                     const float* __restrict__ f2,
                     const float* __restrict__ f3,
                     const float* __restrict__ boxes,
                     float* __restrict__ out)
{
    __shared__ float  s_temp[WARPS][CPW][OUTHW * TSTRIDE];
    __shared__ int4   s_yoff[OUTHW];   // row offsets premultiplied by W
    __shared__ float4 s_yw[OUTHW];     // (hy0, ly0, hy1, ly1)
    __shared__ float  s_f[4];          // x1s, y1s, bin_w, bin_h
    __shared__ int    s_i[2];          // level, W

    const int k   = blockIdx.x >> 4;          // roi  (GRPS = 16)
    const int grp = blockIdx.x & (GRPS - 1);
    const int tid = threadIdx.x;

    // ---- per-roi scalars (thread 0 only) ----
    if (tid == 0) {
        const float* bx = boxes + k * 4;
        float x1 = bx[0], y1 = bx[1], x2 = bx[2], y2 = bx[3];

        float area = (x2 - x1) * (y2 - y1);
        float s    = sqrtf(area);
        float lvl  = floorf(4.0f + log2f(s / 224.0f) + 1e-6f);
        lvl = fminf(fmaxf(lvl, 2.0f), 5.0f);
        int level = (int)lvl - 2;

        const float scales[4] = {0.25f, 0.125f, 0.0625f, 0.03125f};
        const int   dims[4]   = {200, 100, 50, 25};
        float sc = scales[level];
        int   W  = dims[level];

        float x1s = x1 * sc, y1s = y1 * sc;
        float x2s = x2 * sc, y2s = y2 * sc;

        s_f[0] = x1s;
        s_f[1] = y1s;
        s_f[2] = fmaxf(x2s - x1s, 1.0f) / (float)OUTHW;
        s_f[3] = fmaxf(y2s - y1s, 1.0f) / (float)OUTHW;
        s_i[0] = level;
        s_i[1] = W;
    }
    __syncthreads();

    const int   level = s_i[0];
    const int   W     = s_i[1];
    const float x1s   = s_f[0];
    const float y1s   = s_f[1];
    const float bin_w = s_f[2];
    const float bin_h = s_f[3];

    // ---- y tables (threads 0-6) ----
    if (tid < OUTHW) {
        int p = tid;
        float half = bin_h * 0.5f;
        int lo0, hi0, lo1, hi1; float l0, h0, l1, h1;
        prep_coord(y1s + (float)p * bin_h + 0.5f * half, W, lo0, hi0, l0, h0);
        prep_coord(y1s + (float)p * bin_h + 1.5f * half, W, lo1, hi1, l1, h1);
        s_yoff[p] = make_int4(lo0 * W, hi0 * W, lo1 * W, hi1 * W);
        s_yw[p]   = make_float4(h0, l0, h1, l1);
    }
    __syncthreads();

    const int warp = tid >> 5;
    const int lane = tid & 31;
    const int c0   = grp * CPB + warp * CPW;    // first of 2 adjacent channels
    const int b    = k >> 8;

    // ---- per-lane x corner: j = 4*pw + 2*ix + corner (lanes 28-31 mirror 27) ----
    const int j      = (lane < 28) ? lane : 27;
    const int si     = j >> 1;
    const int corner = j & 1;
    const int pwj    = si >> 1;
    const int ixj    = si & 1;

    float half_bw = bin_w * 0.5f;
    int xlo, xhi; float xl, xh;
    prep_coord(x1s + (float)pwj * bin_w + ((float)ixj + 0.5f) * half_bw, W,
               xlo, xhi, xl, xh);
    const int   xc = corner ? xhi : xlo;
    const float xw = 0.25f * (corner ? xl : xh);

    const float* feat;
    switch (level) {
        case 0:  feat = f0; break;
        case 1:  feat = f1; break;
        case 2:  feat = f2; break;
        default: feat = f3; break;
    }
    const int plane = W * W;
    const float* __restrict__ pb0 =
        feat + (size_t)((b * NC + c0) * W) * (size_t)W + xc;
    const float* __restrict__ pb1 = pb0 + plane;

    // ---- phase A: batch ALL 56 loads (2 channels x 28) before any FMA ----
    int4 ro[OUTHW];
    #pragma unroll
    for (int ph = 0; ph < OUTHW; ph++) ro[ph] = s_yoff[ph];

    float v[CPW][OUTHW][4];
    #pragma unroll
    for (int ph = 0; ph < OUTHW; ph++) {
        v[0][ph][0] = __ldg(pb0 + ro[ph].x);
        v[0][ph][1] = __ldg(pb0 + ro[ph].y);
        v[0][ph][2] = __ldg(pb0 + ro[ph].z);
        v[0][ph][3] = __ldg(pb0 + ro[ph].w);
        v[1][ph][0] = __ldg(pb1 + ro[ph].x);
        v[1][ph][1] = __ldg(pb1 + ro[ph].y);
        v[1][ph][2] = __ldg(pb1 + ro[ph].z);
        v[1][ph][3] = __ldg(pb1 + ro[ph].w);
    }

    #pragma unroll
    for (int ch = 0; ch < CPW; ch++) {
        float* __restrict__ tw = s_temp[warp][ch];
        #pragma unroll
        for (int ph = 0; ph < OUTHW; ph++) {
            float4 yw = s_yw[ph];
            float a = yw.x * v[ch][ph][0] + yw.y * v[ch][ph][1]
                    + yw.z * v[ch][ph][2] + yw.w * v[ch][ph][3];
            if (lane < 28) tw[ph * TSTRIDE + j] = a * xw;
        }
    }
    __syncwarp();

    // ---- phase B: 98 contiguous outputs per warp (channels c0, c0+1) ----
    const size_t obase = (size_t)(k * NC + c0) * NBINS;
    #pragma unroll
    for (int o = lane; o < CPW * NBINS; o += 32) {
        int ch = (o >= NBINS);
        int oo = o - ch * NBINS;
        int ph = oo / OUTHW;
        int pw = oo - ph * OUTHW;
        const float* t = s_temp[warp][ch] + ph * TSTRIDE + pw * 4;
        out[obase + o] = (t[0] + t[1]) + (t[2] + t[3]);
    }
}

extern "C" void kernel_launch(void* const* d_in, const int* in_sizes, int n_in,
                              void* d_out, int out_size)
{
    const float* f0    = (const float*)d_in[0];
    const float* f1    = (const float*)d_in[1];
    const float* f2    = (const float*)d_in[2];
    const float* f3    = (const float*)d_in[3];
    const float* boxes = (const float*)d_in[4];
    float* out = (float*)d_out;

    const int blocks = KROIS * GRPS;   // 512 * 16 = 8192
    roi_align_2ch_kernel<<<blocks, 256>>>(f0, f1, f2, f3, boxes, out);
}